// round 2
// baseline (speedup 1.0000x reference)
#include <cuda_runtime.h>
#include <cstdint>

// Problem constants
#define B_   2
#define C_   64
#define H_   192
#define W_   192
#define HW_  (H_*W_)          // 36864
#define KK_  9
#define HP_  194
#define WP_  194
#define HPWP_ (HP_*WP_)       // 37636
#define CI_  65               // C+1
#define OC_  18               // 2*KK
#define RTOT_ 576             // C*KK

// Scratch (device globals; no allocation allowed)
__device__ float g_xp [B_*C_*HPWP_];   // padded x  (~19.3 MB)
__device__ float g_off[B_*OC_*HW_];    // offsets   (~5.3 MB)
__device__ float g_wt [RTOT_*C_];      // transposed weight [576][64]

// ---------------------------------------------------------------------------
// Kernel 1: zero-pad x into g_xp
// ---------------------------------------------------------------------------
__global__ void pad_kernel(const float* __restrict__ x) {
    int idx = blockIdx.x * blockDim.x + threadIdx.x;
    if (idx >= B_*C_*HPWP_) return;
    int pw = idx % WP_;
    int t  = idx / WP_;
    int ph = t % HP_;
    int bc = t / HP_;
    float v = 0.f;
    if (ph >= 1 && ph <= H_ && pw >= 1 && pw <= W_)
        v = x[(size_t)bc * HW_ + (ph - 1) * W_ + (pw - 1)];
    g_xp[idx] = v;
}

// ---------------------------------------------------------------------------
// Kernel 2: transpose weight [64][576] -> g_wt [576][64]
// ---------------------------------------------------------------------------
__global__ void wt_kernel(const float* __restrict__ w) {
    int idx = blockIdx.x * blockDim.x + threadIdx.x;
    if (idx >= C_*RTOT_) return;
    int o = idx / RTOT_;
    int i = idx % RTOT_;
    g_wt[i * C_ + o] = w[idx];
}

// ---------------------------------------------------------------------------
// Kernel 3: offset-predicting conv (unchanged from R0)
// ---------------------------------------------------------------------------
__global__ __launch_bounds__(256) void offconv_kernel(
    const float* __restrict__ x, const float* __restrict__ depth,
    const float* __restrict__ w_off, const float* __restrict__ bias)
{
    __shared__ float w_s[OC_*CI_*KK_];   // 10530 floats, 42.1 KB
    const int tid = threadIdx.x;
    const int b   = blockIdx.y;

    for (int i = tid; i < OC_*CI_*KK_; i += 256) w_s[i] = w_off[i];
    __syncthreads();

    const int p0 = blockIdx.x * 512 + tid;
    const int p1 = p0 + 256;

    int ti0[KK_], ti1[KK_];
    {
        int oh0 = p0 / W_, ow0 = p0 % W_;
        int oh1 = p1 / W_, ow1 = p1 % W_;
        #pragma unroll
        for (int t = 0; t < KK_; ++t) {
            int ky = t / 3 - 1, kx = t % 3 - 1;
            int ih0 = oh0 + ky, iw0 = ow0 + kx;
            int ih1 = oh1 + ky, iw1 = ow1 + kx;
            ti0[t] = (ih0 >= 0 && ih0 < H_ && iw0 >= 0 && iw0 < W_) ? ih0 * W_ + iw0 : -1;
            ti1[t] = (ih1 >= 0 && ih1 < H_ && iw1 >= 0 && iw1 < W_) ? ih1 * W_ + iw1 : -1;
        }
    }

    float acc0[OC_], acc1[OC_];
    #pragma unroll
    for (int o = 0; o < OC_; ++o) { float bo = bias[o]; acc0[o] = bo; acc1[o] = bo; }

    for (int c = 0; c < CI_; ++c) {
        const float* plane = (c < C_) ? (x + ((size_t)b * C_ + c) * HW_)
                                      : (depth + (size_t)b * HW_);
        float v0[KK_], v1[KK_];
        #pragma unroll
        for (int t = 0; t < KK_; ++t) {
            v0[t] = (ti0[t] >= 0) ? plane[ti0[t]] : 0.f;
            v1[t] = (ti1[t] >= 0) ? plane[ti1[t]] : 0.f;
        }
        #pragma unroll
        for (int o = 0; o < OC_; ++o) {
            const float* wp = &w_s[(o * CI_ + c) * KK_];
            #pragma unroll
            for (int t = 0; t < KK_; ++t) {
                float w = wp[t];
                acc0[o] = fmaf(v0[t], w, acc0[o]);
                acc1[o] = fmaf(v1[t], w, acc1[o]);
            }
        }
    }

    #pragma unroll
    for (int o = 0; o < OC_; ++o) {
        g_off[((size_t)b * OC_ + o) * HW_ + p0] = acc0[o];
        g_off[((size_t)b * OC_ + o) * HW_ + p1] = acc1[o];
    }
}

// ---------------------------------------------------------------------------
// Kernel 4: fused bilinear gather + GEMM, v2.
// Tile: 128 pixels x 64 out channels per block. K=576 split into 16 chunks of
// 36 rows (4 input channels x 9 taps). 256 threads, 8px x 4oc micro-tile.
// smem ~40.5 KB -> 4 blocks/SM. LDS bytes per FMA: 1.5 (was 2.0).
// ---------------------------------------------------------------------------
#define TPX_ 128  // pixels per tile
#define CH_  4    // channels per chunk
#define RC_  (CH_*KK_)   // 36 rows per chunk
#define NC_  (C_/CH_)    // 16 chunks

__global__ __launch_bounds__(256) void fused_kernel(float* __restrict__ out)
{
    __shared__ __align__(16) float  cols_s[RC_*TPX_];  // 18432 B
    __shared__ __align__(16) float  w_s   [RC_*C_];    //  9216 B
    __shared__ float2 tap_a  [KK_*TPX_];               //  9216 B
    __shared__ int    tap_idx[KK_*TPX_];               //  4608 B

    const int tid  = threadIdx.x;
    const int b    = blockIdx.y;
    const int pix0 = blockIdx.x * TPX_;

    // ---- phase 0: per-pixel tap coordinates (1152 entries) ----
    for (int e = tid; e < KK_*TPX_; e += 256) {
        int kk = e / TPX_;
        int p  = e % TPX_;
        int pix = pix0 + p;
        int oh = pix / W_, ow = pix % W_;
        float ox = g_off[((size_t)b * OC_ + kk) * HW_ + pix];
        float oy = g_off[((size_t)b * OC_ + KK_ + kk) * HW_ + pix];
        float cx = (float)(oh + 1 + (kk / 3) - 1) + ox;
        float cy = (float)(ow + 1 + (kk % 3) - 1) + oy;
        cx = fminf(fmaxf(cx, 0.f), (float)(HP_ - 1));
        cy = fminf(fmaxf(cy, 0.f), (float)(WP_ - 1));
        int tlx = (int)floorf(cx); tlx = min(max(tlx, 0), HP_ - 2);
        int tly = (int)floorf(cy); tly = min(max(tly, 0), WP_ - 2);
        float ax = cx - (float)tlx;   // frac along x (rows, +WP_)
        float ay = cy - (float)tly;   // frac along y (cols, +1)
        tap_idx[e] = tlx * WP_ + tly;
        tap_a[e]   = make_float2(ax, ay);
    }

    float acc[4][8];
    #pragma unroll
    for (int i = 0; i < 4; ++i)
        #pragma unroll
        for (int j = 0; j < 8; ++j) acc[i][j] = 0.f;

    const int ow_ = tid >> 4;      // 0..15 -> out channels ow_*4..+3
    const int pw_ = tid & 15;      // 0..15 -> pixels pw_*8..+7

    for (int cc = 0; cc < NC_; ++cc) {
        __syncthreads();   // protect smem reuse (also orders phase-0 on cc==0)

        // fill weight tile (coalesced float4 copy from pre-transposed g_wt)
        {
            const float4* wsrc = reinterpret_cast<const float4*>(g_wt + cc * RC_ * C_);
            float4* wdst = reinterpret_cast<float4*>(w_s);
            #pragma unroll
            for (int e = tid; e < RC_ * C_ / 4; e += 256) wdst[e] = wsrc[e];
        }

        // fill cols tile: bilinear gather (lerp form) from padded x
        #pragma unroll 2
        for (int e = tid; e < RC_ * TPX_; e += 256) {
            int r  = e >> 7;           // 0..35
            int p  = e & 127;
            int c  = (cc << 2) + r / KK_;
            int kk = r % KK_;
            int t  = kk * TPX_ + p;
            int idx = tap_idx[t];
            float2 a = tap_a[t];
            const float* xpc = g_xp + ((size_t)b * C_ + c) * HPWP_;
            float x00 = xpc[idx];
            float x01 = xpc[idx + 1];
            float x10 = xpc[idx + WP_];
            float x11 = xpc[idx + WP_ + 1];
            float r0 = fmaf(a.y, x01 - x00, x00);
            float r1 = fmaf(a.y, x11 - x10, x10);
            cols_s[e] = fmaf(a.x, r1 - r0, r0);
        }
        __syncthreads();

        // GEMM micro-kernel: acc[o][p] += w_s[r][o] * cols_s[r][p]
        const float4* w4 = reinterpret_cast<const float4*>(w_s);
        const float4* c4 = reinterpret_cast<const float4*>(cols_s);
        #pragma unroll 4
        for (int r = 0; r < RC_; ++r) {
            float4 wv = w4[r * 16 + ow_];
            float4 ca = c4[r * 32 + pw_ * 2];
            float4 cb = c4[r * 32 + pw_ * 2 + 1];
            acc[0][0] = fmaf(wv.x, ca.x, acc[0][0]);
            acc[0][1] = fmaf(wv.x, ca.y, acc[0][1]);
            acc[0][2] = fmaf(wv.x, ca.z, acc[0][2]);
            acc[0][3] = fmaf(wv.x, ca.w, acc[0][3]);
            acc[0][4] = fmaf(wv.x, cb.x, acc[0][4]);
            acc[0][5] = fmaf(wv.x, cb.y, acc[0][5]);
            acc[0][6] = fmaf(wv.x, cb.z, acc[0][6]);
            acc[0][7] = fmaf(wv.x, cb.w, acc[0][7]);
            acc[1][0] = fmaf(wv.y, ca.x, acc[1][0]);
            acc[1][1] = fmaf(wv.y, ca.y, acc[1][1]);
            acc[1][2] = fmaf(wv.y, ca.z, acc[1][2]);
            acc[1][3] = fmaf(wv.y, ca.w, acc[1][3]);
            acc[1][4] = fmaf(wv.y, cb.x, acc[1][4]);
            acc[1][5] = fmaf(wv.y, cb.y, acc[1][5]);
            acc[1][6] = fmaf(wv.y, cb.z, acc[1][6]);
            acc[1][7] = fmaf(wv.y, cb.w, acc[1][7]);
            acc[2][0] = fmaf(wv.z, ca.x, acc[2][0]);
            acc[2][1] = fmaf(wv.z, ca.y, acc[2][1]);
            acc[2][2] = fmaf(wv.z, ca.z, acc[2][2]);
            acc[2][3] = fmaf(wv.z, ca.w, acc[2][3]);
            acc[2][4] = fmaf(wv.z, cb.x, acc[2][4]);
            acc[2][5] = fmaf(wv.z, cb.y, acc[2][5]);
            acc[2][6] = fmaf(wv.z, cb.z, acc[2][6]);
            acc[2][7] = fmaf(wv.z, cb.w, acc[2][7]);
            acc[3][0] = fmaf(wv.w, ca.x, acc[3][0]);
            acc[3][1] = fmaf(wv.w, ca.y, acc[3][1]);
            acc[3][2] = fmaf(wv.w, ca.z, acc[3][2]);
            acc[3][3] = fmaf(wv.w, ca.w, acc[3][3]);
            acc[3][4] = fmaf(wv.w, cb.x, acc[3][4]);
            acc[3][5] = fmaf(wv.w, cb.y, acc[3][5]);
            acc[3][6] = fmaf(wv.w, cb.z, acc[3][6]);
            acc[3][7] = fmaf(wv.w, cb.w, acc[3][7]);
        }
    }

    // write output: out[b][o][pix], 4 channels x 8 consecutive pixels
    const int o0 = ow_ * 4;
    const int px = pix0 + pw_ * 8;
    #pragma unroll
    for (int i = 0; i < 4; ++i) {
        float* dst = out + ((size_t)b * C_ + o0 + i) * HW_ + px;
        *reinterpret_cast<float4*>(dst)     = make_float4(acc[i][0], acc[i][1], acc[i][2], acc[i][3]);
        *reinterpret_cast<float4*>(dst + 4) = make_float4(acc[i][4], acc[i][5], acc[i][6], acc[i][7]);
    }
}

// ---------------------------------------------------------------------------
// Launch
// ---------------------------------------------------------------------------
extern "C" void kernel_launch(void* const* d_in, const int* in_sizes, int n_in,
                              void* d_out, int out_size) {
    const float* x      = (const float*)d_in[0];  // [2,64,192,192]
    const float* depth  = (const float*)d_in[1];  // [2,1,192,192]
    const float* w_off  = (const float*)d_in[2];  // [18,65,3,3]
    const float* bias   = (const float*)d_in[3];  // [18]
    const float* weight = (const float*)d_in[4];  // [64,64,3,3]
    float* out = (float*)d_out;                   // [2,64,192,192]

    {
        int n = B_*C_*HPWP_;
        pad_kernel<<<(n + 255) / 256, 256>>>(x);
    }
    {
        int n = C_*RTOT_;
        wt_kernel<<<(n + 255) / 256, 256>>>(weight);
    }
    {
        dim3 grid(HW_ / 512, B_);
        offconv_kernel<<<grid, 256>>>(x, depth, w_off, bias);
    }
    {
        dim3 grid(HW_ / TPX_, B_);
        fused_kernel<<<grid, 256>>>(out);
    }
}

// round 4
// speedup vs baseline: 1.6339x; 1.6339x over previous
#include <cuda_runtime.h>
#include <cuda_bf16.h>
#include <cstdint>
#include <cstring>

// Problem constants
#define B_   2
#define C_   64
#define H_   192
#define W_   192
#define HW_  (H_*W_)          // 36864
#define KK_  9
#define HP_  194
#define WP_  194
#define HPWP_ (HP_*WP_)       // 37636
#define CI_  65               // C+1
#define OC_  18               // 2*KK

// Scratch (device globals)
__device__ float    g_xp  [B_*HPWP_*C_];     // padded x, NHWC  (~19.3 MB)
__device__ float    g_off [B_*OC_*HW_];      // offsets (~5.3 MB)
__device__ uint16_t g_wtbh[KK_*C_*C_];       // weight hi bf16, [kk][oc][c]
__device__ uint16_t g_wtbl[KK_*C_*C_];       // weight lo bf16

// ---------------------------------------------------------------------------
// helpers
// ---------------------------------------------------------------------------
__device__ __forceinline__ uint32_t cvt_bf16x2(float hi, float lo) {
    uint32_t r;
    asm("cvt.rn.satfinite.bf16x2.f32 %0, %1, %2;" : "=r"(r) : "f"(hi), "f"(lo));
    return r;
}

__device__ __forceinline__ void mma16816(float& d0, float& d1, float& d2, float& d3,
                                         uint32_t a0, uint32_t a1, uint32_t a2, uint32_t a3,
                                         uint32_t b0, uint32_t b1) {
    asm volatile("mma.sync.aligned.m16n8k16.row.col.f32.bf16.bf16.f32 "
                 "{%0,%1,%2,%3},{%4,%5,%6,%7},{%8,%9},{%0,%1,%2,%3};"
                 : "+f"(d0), "+f"(d1), "+f"(d2), "+f"(d3)
                 : "r"(a0), "r"(a1), "r"(a2), "r"(a3), "r"(b0), "r"(b1));
}

// ---------------------------------------------------------------------------
// Kernel 1a: zero g_xp
// ---------------------------------------------------------------------------
__global__ void zero_xp_kernel() {
    int i = blockIdx.x * blockDim.x + threadIdx.x;
    if (i < B_*HPWP_*C_/4)
        reinterpret_cast<float4*>(g_xp)[i] = make_float4(0.f, 0.f, 0.f, 0.f);
}

// ---------------------------------------------------------------------------
// Kernel 1b: NCHW -> padded NHWC transpose (interior)
// ---------------------------------------------------------------------------
__global__ __launch_bounds__(256) void nhwc_kernel(const float* __restrict__ x) {
    __shared__ float tile[C_][33];
    const int tid = threadIdx.x;
    const int b   = blockIdx.y;
    const int pix0 = blockIdx.x * 32;

    {
        int ty = tid >> 5, tx = tid & 31;
        #pragma unroll
        for (int c0 = 0; c0 < C_; c0 += 8)
            tile[c0 + ty][tx] = x[((size_t)b * C_ + c0 + ty) * HW_ + pix0 + tx];
    }
    __syncthreads();
    {
        int pi = tid >> 6, c = tid & 63;
        #pragma unroll
        for (int j = 0; j < 8; ++j) {
            int pix = pix0 + j * 4 + pi;
            int ph = pix / W_ + 1, pw = pix % W_ + 1;
            g_xp[((size_t)b * HPWP_ + ph * WP_ + pw) * C_ + c] = tile[c][j * 4 + pi];
        }
    }
}

// ---------------------------------------------------------------------------
// Kernel 2: weight -> bf16 hi/lo, layout [kk][oc][c]
// ---------------------------------------------------------------------------
__global__ void wprep_kernel(const float* __restrict__ w) {
    int i = blockIdx.x * blockDim.x + threadIdx.x;
    if (i >= KK_*C_*C_) return;
    int kk = i / (C_*C_);
    int oc = (i >> 6) & 63;
    int c  = i & 63;
    float v = w[oc * 576 + c * KK_ + kk];
    __nv_bfloat16 h = __float2bfloat16(v);
    float hf = __bfloat162float(h);
    __nv_bfloat16 l = __float2bfloat16(v - hf);
    uint16_t hb, lb;
    memcpy(&hb, &h, 2); memcpy(&lb, &l, 2);
    g_wtbh[(kk * C_ + oc) * C_ + c] = hb;
    g_wtbl[(kk * C_ + oc) * C_ + c] = lb;
}

// ---------------------------------------------------------------------------
// Kernel 3: offset-predicting conv (R0 proven version)
// ---------------------------------------------------------------------------
__global__ __launch_bounds__(256) void offconv_kernel(
    const float* __restrict__ x, const float* __restrict__ depth,
    const float* __restrict__ w_off, const float* __restrict__ bias)
{
    __shared__ float w_s[OC_*CI_*KK_];   // 42.1 KB
    const int tid = threadIdx.x;
    const int b   = blockIdx.y;

    for (int i = tid; i < OC_*CI_*KK_; i += 256) w_s[i] = w_off[i];
    __syncthreads();

    const int p0 = blockIdx.x * 512 + tid;
    const int p1 = p0 + 256;

    int ti0[KK_], ti1[KK_];
    {
        int oh0 = p0 / W_, ow0 = p0 % W_;
        int oh1 = p1 / W_, ow1 = p1 % W_;
        #pragma unroll
        for (int t = 0; t < KK_; ++t) {
            int ky = t / 3 - 1, kx = t % 3 - 1;
            int ih0 = oh0 + ky, iw0 = ow0 + kx;
            int ih1 = oh1 + ky, iw1 = ow1 + kx;
            ti0[t] = (ih0 >= 0 && ih0 < H_ && iw0 >= 0 && iw0 < W_) ? ih0 * W_ + iw0 : -1;
            ti1[t] = (ih1 >= 0 && ih1 < H_ && iw1 >= 0 && iw1 < W_) ? ih1 * W_ + iw1 : -1;
        }
    }

    float acc0[OC_], acc1[OC_];
    #pragma unroll
    for (int o = 0; o < OC_; ++o) { float bo = bias[o]; acc0[o] = bo; acc1[o] = bo; }

    for (int c = 0; c < CI_; ++c) {
        const float* plane = (c < C_) ? (x + ((size_t)b * C_ + c) * HW_)
                                      : (depth + (size_t)b * HW_);
        float v0[KK_], v1[KK_];
        #pragma unroll
        for (int t = 0; t < KK_; ++t) {
            v0[t] = (ti0[t] >= 0) ? plane[ti0[t]] : 0.f;
            v1[t] = (ti1[t] >= 0) ? plane[ti1[t]] : 0.f;
        }
        #pragma unroll
        for (int o = 0; o < OC_; ++o) {
            const float* wp = &w_s[(o * CI_ + c) * KK_];
            #pragma unroll
            for (int t = 0; t < KK_; ++t) {
                float w = wp[t];
                acc0[o] = fmaf(v0[t], w, acc0[o]);
                acc1[o] = fmaf(v1[t], w, acc1[o]);
            }
        }
    }

    #pragma unroll
    for (int o = 0; o < OC_; ++o) {
        g_off[((size_t)b * OC_ + o) * HW_ + p0] = acc0[o];
        g_off[((size_t)b * OC_ + o) * HW_ + p1] = acc1[o];
    }
}

// ---------------------------------------------------------------------------
// Kernel 4: fused bilinear gather + mma.sync bf16 GEMM (3-term hi/lo split).
// Block: 64 pixels (M) x 64 out-channels (N), 128 threads (4 warps).
// Warp tile: 32 px x 32 oc. K = 576 as 9 kk-chunks of 64 channels.
// A tiles in smem (pitch 72 bf16, conflict-free fragment loads).
// B fragments read directly from global (L1/L2-resident, 37 KB total).
// ---------------------------------------------------------------------------
#define APITCH_ 72

__global__ __launch_bounds__(128) void fused_mma_kernel(float* __restrict__ out)
{
    __shared__ __align__(16) uint16_t Ahi[64 * APITCH_];   // 9216 B
    __shared__ __align__(16) uint16_t Alo[64 * APITCH_];   // 9216 B
    __shared__ int    tap_idx[64];
    __shared__ float2 tap_a  [64];

    const int tid  = threadIdx.x;
    const int wid  = tid >> 5;
    const int lane = tid & 31;
    const int b    = blockIdx.y;
    const int pix0 = blockIdx.x * 64;

    const int pxg = wid & 1;    // 0/1: pixel group (32 px)
    const int ocg = wid >> 1;   // 0/1: oc group (32 oc)

    float acc[2][4][4];
    #pragma unroll
    for (int mi = 0; mi < 2; ++mi)
        #pragma unroll
        for (int ni = 0; ni < 4; ++ni)
            #pragma unroll
            for (int r = 0; r < 4; ++r) acc[mi][ni][r] = 0.f;

    const float* xb = g_xp + (size_t)b * HPWP_ * C_;
    const int cg = tid & 15;    // channel group (4 ch)
    const int pb = tid >> 4;    // 0..7

    for (int kk = 0; kk < KK_; ++kk) {
        __syncthreads();   // A smem free (prev mma fragment loads complete)

        // --- taps for this kk (64 pixels) ---
        if (tid < 64) {
            int pix = pix0 + tid;
            int oh = pix / W_, ow = pix % W_;
            float ox = g_off[((size_t)b * OC_ + kk) * HW_ + pix];
            float oy = g_off[((size_t)b * OC_ + KK_ + kk) * HW_ + pix];
            float cx = (float)(oh + kk / 3) + ox;
            float cy = (float)(ow + kk % 3) + oy;
            cx = fminf(fmaxf(cx, 0.f), (float)(HP_ - 1));
            cy = fminf(fmaxf(cy, 0.f), (float)(WP_ - 1));
            int tlx = (int)floorf(cx); tlx = min(max(tlx, 0), HP_ - 2);
            int tly = (int)floorf(cy); tly = min(max(tly, 0), WP_ - 2);
            tap_idx[tid] = tlx * WP_ + tly;
            tap_a[tid] = make_float2(cx - (float)tlx, cy - (float)tly);
        }
        __syncthreads();

        // --- gather: 64 px x 64 ch -> Ahi/Alo bf16 tiles ---
        #pragma unroll 2
        for (int i = 0; i < 8; ++i) {
            int p = pb + 8 * i;
            int idx = tap_idx[p];
            float2 a = tap_a[p];
            const float4* q = reinterpret_cast<const float4*>(xb + (size_t)idx * C_) + cg;
            float4 x00 = q[0];
            float4 x01 = q[16];           // +1 col (NHWC: +64 floats)
            float4 x10 = q[WP_ * 16];     // +1 row
            float4 x11 = q[(WP_ + 1) * 16];
            float4 v;
            {
                float r0, r1;
                r0 = fmaf(a.y, x01.x - x00.x, x00.x);
                r1 = fmaf(a.y, x11.x - x10.x, x10.x);
                v.x = fmaf(a.x, r1 - r0, r0);
                r0 = fmaf(a.y, x01.y - x00.y, x00.y);
                r1 = fmaf(a.y, x11.y - x10.y, x10.y);
                v.y = fmaf(a.x, r1 - r0, r0);
                r0 = fmaf(a.y, x01.z - x00.z, x00.z);
                r1 = fmaf(a.y, x11.z - x10.z, x10.z);
                v.z = fmaf(a.x, r1 - r0, r0);
                r0 = fmaf(a.y, x01.w - x00.w, x00.w);
                r1 = fmaf(a.y, x11.w - x10.w, x10.w);
                v.w = fmaf(a.x, r1 - r0, r0);
            }
            uint32_t h01 = cvt_bf16x2(v.y, v.x);   // lo16=v.x, hi16=v.y
            uint32_t h23 = cvt_bf16x2(v.w, v.z);
            float l0 = v.x - __uint_as_float(h01 << 16);
            float l1 = v.y - __uint_as_float(h01 & 0xFFFF0000u);
            float l2 = v.z - __uint_as_float(h23 << 16);
            float l3 = v.w - __uint_as_float(h23 & 0xFFFF0000u);
            uint32_t q01 = cvt_bf16x2(l1, l0);
            uint32_t q23 = cvt_bf16x2(l3, l2);
            int eo = p * APITCH_ + cg * 4;
            *reinterpret_cast<uint2*>(&Ahi[eo]) = make_uint2(h01, h23);
            *reinterpret_cast<uint2*>(&Alo[eo]) = make_uint2(q01, q23);
        }
        __syncthreads();

        // --- mma: warp tile 32px x 32oc, K=64 ---
        const uint16_t* wh = g_wtbh + kk * (C_*C_);
        const uint16_t* wl = g_wtbl + kk * (C_*C_);
        const int arow = pxg * 32 + (lane >> 2);      // + mi*16 (+8 for a1/a3)
        const int akol = (lane & 3) * 2;              // + ki*16 (+8 for a2/a3)
        const int brow = ocg * 32 + (lane >> 2);      // + ni*8

        #pragma unroll
        for (int ki = 0; ki < 4; ++ki) {
            const int k0 = ki * 16 + akol;
            uint32_t ah[2][4], al[2][4];
            #pragma unroll
            for (int mi = 0; mi < 2; ++mi) {
                int r0 = (arow + mi * 16) * APITCH_ + k0;
                int r1 = r0 + 8 * APITCH_;
                ah[mi][0] = *reinterpret_cast<const uint32_t*>(&Ahi[r0]);
                ah[mi][1] = *reinterpret_cast<const uint32_t*>(&Ahi[r1]);
                ah[mi][2] = *reinterpret_cast<const uint32_t*>(&Ahi[r0 + 8]);
                ah[mi][3] = *reinterpret_cast<const uint32_t*>(&Ahi[r1 + 8]);
                al[mi][0] = *reinterpret_cast<const uint32_t*>(&Alo[r0]);
                al[mi][1] = *reinterpret_cast<const uint32_t*>(&Alo[r1]);
                al[mi][2] = *reinterpret_cast<const uint32_t*>(&Alo[r0 + 8]);
                al[mi][3] = *reinterpret_cast<const uint32_t*>(&Alo[r1 + 8]);
            }
            #pragma unroll
            for (int ni = 0; ni < 4; ++ni) {
                int boff = (brow + ni * 8) * C_ + k0;
                uint32_t bh0 = *reinterpret_cast<const uint32_t*>(wh + boff);
                uint32_t bh1 = *reinterpret_cast<const uint32_t*>(wh + boff + 8);
                uint32_t bl0 = *reinterpret_cast<const uint32_t*>(wl + boff);
                uint32_t bl1 = *reinterpret_cast<const uint32_t*>(wl + boff + 8);
                #pragma unroll
                for (int mi = 0; mi < 2; ++mi) {
                    float* d = acc[mi][ni];
                    mma16816(d[0], d[1], d[2], d[3],
                             ah[mi][0], ah[mi][1], ah[mi][2], ah[mi][3], bh0, bh1);
                    mma16816(d[0], d[1], d[2], d[3],
                             al[mi][0], al[mi][1], al[mi][2], al[mi][3], bh0, bh1);
                    mma16816(d[0], d[1], d[2], d[3],
                             ah[mi][0], ah[mi][1], ah[mi][2], ah[mi][3], bl0, bl1);
                }
            }
        }
    }

    // --- epilogue: D fragment -> out[b][oc][pix] ---
    #pragma unroll
    for (int mi = 0; mi < 2; ++mi) {
        int px = pix0 + pxg * 32 + mi * 16 + (lane >> 2);
        #pragma unroll
        for (int ni = 0; ni < 4; ++ni) {
            int oc = ocg * 32 + ni * 8 + (lane & 3) * 2;
            float* o0 = out + ((size_t)b * C_ + oc) * HW_;
            float* o1 = out + ((size_t)b * C_ + oc + 1) * HW_;
            o0[px]     = acc[mi][ni][0];
            o1[px]     = acc[mi][ni][1];
            o0[px + 8] = acc[mi][ni][2];
            o1[px + 8] = acc[mi][ni][3];
        }
    }
}

// ---------------------------------------------------------------------------
// Launch
// ---------------------------------------------------------------------------
extern "C" void kernel_launch(void* const* d_in, const int* in_sizes, int n_in,
                              void* d_out, int out_size) {
    const float* x      = (const float*)d_in[0];
    const float* depth  = (const float*)d_in[1];
    const float* w_off  = (const float*)d_in[2];
    const float* bias   = (const float*)d_in[3];
    const float* weight = (const float*)d_in[4];
    float* out = (float*)d_out;

    {
        int n = B_*HPWP_*C_/4;
        zero_xp_kernel<<<(n + 255) / 256, 256>>>();
    }
    {
        dim3 grid(HW_ / 32, B_);
        nhwc_kernel<<<grid, 256>>>(x);
    }
    {
        int n = KK_*C_*C_;
        wprep_kernel<<<(n + 255) / 256, 256>>>(weight);
    }
    {
        dim3 grid(HW_ / 512, B_);
        offconv_kernel<<<grid, 256>>>(x, depth, w_off, bias);
    }
    {
        dim3 grid(HW_ / 64, B_);
        fused_mma_kernel<<<grid, 128>>>(out);
    }
}